// round 16
// baseline (speedup 1.0000x reference)
#include <cuda_runtime.h>
#include <cuda_bf16.h>
#include <cstdint>

#define B_ 128
#define T_ 128
#define D_ 2048
#define U_ 512

// ================= device scratch =================
__device__ float g_xproj[(size_t)B_ * T_ * U_];          // 32 MB
__device__ float g_H[2][B_ * U_];                        // ping-pong pre-LN state
__device__ int   g_bar[16];
// bf16 hi/lo planes for the x-projection GEMM
__device__ __nv_bfloat16 g_Ahi[(size_t)16384 * 2048];    // 64 MB
__device__ __nv_bfloat16 g_Alo[(size_t)16384 * 2048];    // 64 MB
__device__ __nv_bfloat16 g_Bhi[(size_t)512 * 2048];      // w_in^T hi
__device__ __nv_bfloat16 g_Blo[(size_t)512 * 2048];      // w_in^T lo
// w_rec^T hi/lo ([c][k], k contiguous) for the scan tensor-core GEMM
__device__ __nv_bfloat16 g_WThi[(size_t)512 * 512];      // 512 KB
__device__ __nv_bfloat16 g_WTlo[(size_t)512 * 512];      // 512 KB

// ================= helpers =================
__device__ __forceinline__ uint32_t smem_u32(const void* p) {
    uint32_t a;
    asm("{ .reg .u64 t; cvta.to.shared.u64 t, %1; cvt.u32.u64 %0, t; }" : "=r"(a) : "l"(p));
    return a;
}
__device__ __forceinline__ void cp_async16(uint32_t dst, const void* src) {
    asm volatile("cp.async.cg.shared.global [%0], [%1], 16;" :: "r"(dst), "l"(src) : "memory");
}
__device__ __forceinline__ void ldmatrix_x4(uint32_t& d0, uint32_t& d1, uint32_t& d2, uint32_t& d3,
                                            uint32_t addr) {
    asm volatile("ldmatrix.sync.aligned.m8n8.x4.shared.b16 {%0,%1,%2,%3}, [%4];"
                 : "=r"(d0), "=r"(d1), "=r"(d2), "=r"(d3) : "r"(addr));
}
__device__ __forceinline__ void mma16816(float* c, const uint32_t* a, const uint32_t* b) {
    asm volatile("mma.sync.aligned.m16n8k16.row.col.f32.bf16.bf16.f32 "
                 "{%0,%1,%2,%3}, {%4,%5,%6,%7}, {%8,%9}, {%0,%1,%2,%3};"
                 : "+f"(c[0]), "+f"(c[1]), "+f"(c[2]), "+f"(c[3])
                 : "r"(a[0]), "r"(a[1]), "r"(a[2]), "r"(a[3]), "r"(b[0]), "r"(b[1]));
}
__device__ __forceinline__ void bar_arrive_release(int* addr) {
    asm volatile("red.release.gpu.global.add.s32 [%0], 1;" :: "l"(addr) : "memory");
}
__device__ __forceinline__ int ld_acquire(const int* addr) {
    int v;
    asm volatile("ld.acquire.gpu.global.s32 %0, [%1];" : "=r"(v) : "l"(addr) : "memory");
    return v;
}

// ================= conv: x -> hi/lo bf16 planes =================
__global__ void __launch_bounds__(256) conv_x(const float* __restrict__ x) {
    const size_t i = (size_t)blockIdx.x * 256 + threadIdx.x;
    const size_t e0 = i * 8;
    float4 v0 = *(const float4*)(x + e0);
    float4 v1 = *(const float4*)(x + e0 + 4);
    float v[8] = {v0.x, v0.y, v0.z, v0.w, v1.x, v1.y, v1.z, v1.w};
    unsigned short hs[8], ls[8];
#pragma unroll
    for (int j = 0; j < 8; j++) {
        __nv_bfloat16 h = __float2bfloat16(v[j]);
        __nv_bfloat16 l = __float2bfloat16(v[j] - __bfloat162float(h));
        hs[j] = __bfloat16_as_ushort(h);
        ls[j] = __bfloat16_as_ushort(l);
    }
    uint4 ph, pl;
    ph.x = hs[0] | ((uint32_t)hs[1] << 16); ph.y = hs[2] | ((uint32_t)hs[3] << 16);
    ph.z = hs[4] | ((uint32_t)hs[5] << 16); ph.w = hs[6] | ((uint32_t)hs[7] << 16);
    pl.x = ls[0] | ((uint32_t)ls[1] << 16); pl.y = ls[2] | ((uint32_t)ls[3] << 16);
    pl.z = ls[4] | ((uint32_t)ls[5] << 16); pl.w = ls[6] | ((uint32_t)ls[7] << 16);
    *(uint4*)(g_Ahi + e0) = ph;
    *(uint4*)(g_Alo + e0) = pl;
}

// ================= conv: w_in [2048][512] -> w^T hi/lo [512][2048] =================
__global__ void __launch_bounds__(256) conv_w(const float* __restrict__ w) {
    __shared__ float ts[32][33];
    const int tid = threadIdx.x;
    const int bu = blockIdx.x;
    const int bd = blockIdx.y;
    const int tx = tid & 31, ty = tid >> 5;
#pragma unroll
    for (int j = 0; j < 4; j++) {
        const int dl = ty + 8 * j;
        ts[dl][tx] = w[(size_t)(bd * 32 + dl) * U_ + bu * 32 + tx];
    }
    __syncthreads();
    const int ul = tid >> 3, kg = (tid & 7) * 4;
    const int u = bu * 32 + ul;
    const int kk = bd * 32 + kg;
    unsigned short hs[4], ls[4];
#pragma unroll
    for (int j = 0; j < 4; j++) {
        const float vv = ts[kg + j][ul];
        __nv_bfloat16 h = __float2bfloat16(vv);
        __nv_bfloat16 l = __float2bfloat16(vv - __bfloat162float(h));
        hs[j] = __bfloat16_as_ushort(h);
        ls[j] = __bfloat16_as_ushort(l);
    }
    uint2 ph, pl;
    ph.x = hs[0] | ((uint32_t)hs[1] << 16); ph.y = hs[2] | ((uint32_t)hs[3] << 16);
    pl.x = ls[0] | ((uint32_t)ls[1] << 16); pl.y = ls[2] | ((uint32_t)ls[3] << 16);
    *(uint2*)(g_Bhi + (size_t)u * D_ + kk) = ph;
    *(uint2*)(g_Blo + (size_t)u * D_ + kk) = pl;
}

// ================= conv: w_rec [512][512] -> w_rec^T hi/lo [512][512] =================
__global__ void __launch_bounds__(256) conv_wrec(const float* __restrict__ w) {
    __shared__ float ts[32][33];
    const int tid = threadIdx.x;
    const int bc = blockIdx.x;
    const int bk = blockIdx.y;
    const int tx = tid & 31, ty = tid >> 5;
#pragma unroll
    for (int j = 0; j < 4; j++) {
        const int dl = ty + 8 * j;
        ts[dl][tx] = w[(size_t)(bk * 32 + dl) * U_ + bc * 32 + tx];
    }
    __syncthreads();
    const int ul = tid >> 3, kg = (tid & 7) * 4;
    const int c = bc * 32 + ul;
    const int kk = bk * 32 + kg;
    unsigned short hs[4], ls[4];
#pragma unroll
    for (int j = 0; j < 4; j++) {
        const float vv = ts[kg + j][ul];
        __nv_bfloat16 h = __float2bfloat16(vv);
        __nv_bfloat16 l = __float2bfloat16(vv - __bfloat162float(h));
        hs[j] = __bfloat16_as_ushort(h);
        ls[j] = __bfloat16_as_ushort(l);
    }
    uint2 ph, pl;
    ph.x = hs[0] | ((uint32_t)hs[1] << 16); ph.y = hs[2] | ((uint32_t)hs[3] << 16);
    pl.x = ls[0] | ((uint32_t)ls[1] << 16); pl.y = ls[2] | ((uint32_t)ls[3] << 16);
    *(uint2*)(g_WThi + (size_t)c * U_ + kk) = ph;
    *(uint2*)(g_WTlo + (size_t)c * U_ + kk) = pl;
}

// ================= mma.sync GEMM: 128x256 tile, 64x64 warp tiles (proven) ==========
__global__ void __launch_bounds__(256, 1) gemm_mma(const float* __restrict__ bias) {
    extern __shared__ char sm[];
    const uint32_t sb = smem_u32(sm);
    const int tid = threadIdx.x, lane = tid & 31, wid = tid >> 5;
    const int wm = wid & 1;
    const int wn = wid >> 1;
    const int bn = blockIdx.x;
    const int bm = blockIdx.y;

    float acc[4][8][4];
#pragma unroll
    for (int mi = 0; mi < 4; mi++)
#pragma unroll
        for (int nj = 0; nj < 8; nj++)
#pragma unroll
            for (int e = 0; e < 4; e++) acc[mi][nj][e] = 0.f;

    auto load_stage = [&](int s, int kch) {
        const int seg = kch >> 5, ck = kch & 31;
        const __nv_bfloat16* Ab = (seg < 2) ? g_Ahi : g_Alo;
        const __nv_bfloat16* Bb = (seg == 1) ? g_Blo : g_Bhi;
        const uint32_t sA = sb + s * 49152;
        const uint32_t sB = sA + 16384;
#pragma unroll
        for (int i = 0; i < 4; i++) {
            const int cid = tid + 256 * i;
            const int r = cid >> 3, c = cid & 7;
            const uint32_t sw = (uint32_t)((c ^ (r & 7)) << 4);
            cp_async16(sA + r * 128 + sw,
                       Ab + (size_t)(bm * 128 + r) * D_ + ck * 64 + c * 8);
        }
#pragma unroll
        for (int i = 0; i < 8; i++) {
            const int cid = tid + 256 * i;
            const int r = cid >> 3, c = cid & 7;
            const uint32_t sw = (uint32_t)((c ^ (r & 7)) << 4);
            cp_async16(sB + r * 128 + sw,
                       Bb + (size_t)(bn * 256 + r) * D_ + ck * 64 + c * 8);
        }
    };

    load_stage(0, 0);
    asm volatile("cp.async.commit_group;" ::: "memory");
    load_stage(1, 1);
    asm volatile("cp.async.commit_group;" ::: "memory");

    for (int k = 0; k < 96; k++) {
        asm volatile("cp.async.wait_group 1;" ::: "memory");
        __syncthreads();
        if (k + 2 < 96) load_stage((k + 2) % 3, k + 2);
        asm volatile("cp.async.commit_group;" ::: "memory");

        const uint32_t sA = sb + (k % 3) * 49152;
        const uint32_t sB = sA + 16384;
#pragma unroll
        for (int kk = 0; kk < 4; kk++) {
            uint32_t aF[4][4];
#pragma unroll
            for (int mi = 0; mi < 4; mi++) {
                const int row = wm * 64 + mi * 16 + (lane & 15);
                const int ch = kk * 2 + (lane >> 4);
                ldmatrix_x4(aF[mi][0], aF[mi][1], aF[mi][2], aF[mi][3],
                            sA + row * 128 + ((ch ^ (row & 7)) << 4));
            }
            uint32_t bF[8][2];
#pragma unroll
            for (int ni = 0; ni < 4; ni++) {
                const int row = wn * 64 + ni * 16 + (lane & 7) + ((lane & 16) >> 1);
                const int ch = kk * 2 + ((lane & 8) >> 3);
                uint32_t r0, r1, r2, r3;
                ldmatrix_x4(r0, r1, r2, r3, sB + row * 128 + ((ch ^ (row & 7)) << 4));
                bF[2 * ni][0] = r0; bF[2 * ni][1] = r1;
                bF[2 * ni + 1][0] = r2; bF[2 * ni + 1][1] = r3;
            }
#pragma unroll
            for (int mi = 0; mi < 4; mi++)
#pragma unroll
                for (int nj = 0; nj < 8; nj++)
                    mma16816(acc[mi][nj], aF[mi], bF[nj]);
        }
    }

#pragma unroll
    for (int mi = 0; mi < 4; mi++) {
        const int row = bm * 128 + wm * 64 + mi * 16 + (lane >> 2);
#pragma unroll
        for (int nj = 0; nj < 8; nj++) {
            const int col = bn * 256 + wn * 64 + nj * 8 + (lane & 3) * 2;
            const float2 bi = *(const float2*)&bias[col];
            float2 v0, v1;
            v0.x = acc[mi][nj][0] + bi.x;
            v0.y = acc[mi][nj][1] + bi.y;
            v1.x = acc[mi][nj][2] + bi.x;
            v1.y = acc[mi][nj][3] + bi.y;
            *(float2*)&g_xproj[(size_t)row * U_ + col] = v0;
            *(float2*)&g_xproj[(size_t)(row + 8) * U_ + col] = v1;
        }
    }
}

// ================= scan: warp-granular barrier, double-buffered A, h0 from A tile ====
// smem: A[2][16KB] @0 | WHI 64KB @32768 | WLO 64KB @98304 | GB 4KB @163840
#define OFF_A    0
#define OFF_WHI  32768
#define OFF_WLO  98304
#define OFF_GB   163840
#define SCAN_SMEM 167936

__global__ void __launch_bounds__(256, 1) liquid_scan(const float* __restrict__ tau,
                                                      const float* __restrict__ gamma,
                                                      const float* __restrict__ beta,
                                                      float* __restrict__ out) {
    extern __shared__ char sm[];
    const uint32_t sb = smem_u32(sm);
    float* GB = (float*)(sm + OFF_GB);

    const int tid = threadIdx.x;
    const int lane = tid & 31;
    const int warp = tid >> 5;
    const int bblk = blockIdx.x >> 3;
    const int cblk = blockIdx.x & 7;
    const int rb = bblk * 8;
    const int cb = cblk * 64;

    const int r_up = lane >> 2;
    const int cl_up = warp * 8 + (lane & 3) * 2;
    const int b_up = rb + r_up;
    const int col_up = cb + cl_up;

    // ---- preload W slice (128 KB) + gamma/beta ----
    for (int i = tid; i < 4096; i += 256) {
        const int row = i >> 6, ch = i & 63;
        const uint32_t sw = (uint32_t)((ch ^ (row & 7)) << 4);
        cp_async16(sb + OFF_WHI + row * 1024 + sw, g_WThi + (size_t)(cb + row) * U_ + ch * 8);
        cp_async16(sb + OFF_WLO + row * 1024 + sw, g_WTlo + (size_t)(cb + row) * U_ + ch * 8);
    }
    asm volatile("cp.async.commit_group;" ::: "memory");
    for (int i = tid; i < U_; i += 256) {
        GB[i] = gamma[i];
        GB[U_ + i] = beta[i];
    }
    const float2 tau2 = *(const float2*)&tau[col_up];
    asm volatile("cp.async.wait_group 0;" ::: "memory");
    __syncthreads();

    // GEMM addressing constants
    const uint32_t aRowBase = sb + OFF_A + (lane & 15) * 1024;
    const int aOff = lane >> 4;
    const int aSw = lane & 7;
    const uint32_t bRowHi = sb + OFF_WHI + (warp * 8 + (lane & 7)) * 1024;
    const uint32_t bRowLo = bRowHi + 65536;
    const int bOff = (lane >> 3) & 3;
    const int bSw = lane & 7;

    // ---- hoist ALL B (W) fragments into registers ----
    uint32_t Bh[64], Bl[64];
#pragma unroll
    for (int i = 0; i < 16; i++) {
        const uint32_t off = (uint32_t)((((4 * i + bOff) ^ bSw)) << 4);
        ldmatrix_x4(Bh[4 * i], Bh[4 * i + 1], Bh[4 * i + 2], Bh[4 * i + 3], bRowHi + off);
        ldmatrix_x4(Bl[4 * i], Bl[4 * i + 1], Bl[4 * i + 2], Bl[4 * i + 3], bRowLo + off);
    }

    // h0 (NORMALIZED h) readback address within the A tile
    const uint32_t h0chunk = (uint32_t)((cb >> 3) + warp);
    const uint32_t h0off = (uint32_t)((lane & 3) * 4);

    for (int t = 0; t < T_; t++) {
        const int pr = t & 1;
        const int pw = pr ^ 1;
        const uint32_t aplane = (uint32_t)(pr * 16384);

        // prefetch xp (independent of barrier)
        const float2 xp = *(const float2*)&g_xproj[((size_t)b_up * T_ + t) * U_ + col_up];

        // ---- per-warp wait for all 64 warps of the row-block to finish step t-1 ----
        if (t > 0) {
            if (lane == 0) {
                const int tgt = 64 * t;
                while (ld_acquire(&g_bar[bblk]) < tgt) { }
            }
            __syncwarp();
        }

        // ---- phase L: warp w loads row w of g_H[pr], stats, normalize, split ----
        if (t == 0) {
#pragma unroll
            for (int i = 0; i < 4; i++)
                *(uint4*)(sm + OFF_A + tid * 16 + i * 4096) = make_uint4(0, 0, 0, 0);
        } else {
            const float4* Hg = (const float4*)&g_H[pr][(size_t)(rb + warp) * U_];
            float4 hv[4];
#pragma unroll
            for (int j = 0; j < 4; j++) hv[j] = __ldcg(&Hg[lane * 4 + j]);
            float s = 0.f, q = 0.f;
#pragma unroll
            for (int j = 0; j < 4; j++) {
                s += hv[j].x + hv[j].y + hv[j].z + hv[j].w;
                q += hv[j].x * hv[j].x + hv[j].y * hv[j].y
                   + hv[j].z * hv[j].z + hv[j].w * hv[j].w;
            }
#pragma unroll
            for (int o = 16; o > 0; o >>= 1) {
                s += __shfl_xor_sync(0xffffffffu, s, o);
                q += __shfl_xor_sync(0xffffffffu, q, o);
            }
            const float mean = s * (1.f / 512.f);
            const float var = q * (1.f / 512.f) - mean * mean;
            const float rstd = rsqrtf(var + 1e-3f);
#pragma unroll
            for (int hf = 0; hf < 2; hf++) {
                float vals[8];
                *(float4*)&vals[0] = hv[hf * 2];
                *(float4*)&vals[4] = hv[hf * 2 + 1];
                unsigned short hi[8], lo[8];
#pragma unroll
                for (int e = 0; e < 8; e++) {
                    const int c = lane * 16 + hf * 8 + e;
                    const float n = GB[c] * (vals[e] - mean) * rstd + GB[U_ + c];
                    __nv_bfloat16 h = __float2bfloat16(n);
                    __nv_bfloat16 l = __float2bfloat16(n - __bfloat162float(h));
                    hi[e] = __bfloat16_as_ushort(h);
                    lo[e] = __bfloat16_as_ushort(l);
                }
                uint4 ph, pl;
                ph.x = hi[0] | ((uint32_t)hi[1] << 16); ph.y = hi[2] | ((uint32_t)hi[3] << 16);
                ph.z = hi[4] | ((uint32_t)hi[5] << 16); ph.w = hi[6] | ((uint32_t)hi[7] << 16);
                pl.x = lo[0] | ((uint32_t)lo[1] << 16); pl.y = lo[2] | ((uint32_t)lo[3] << 16);
                pl.z = lo[4] | ((uint32_t)lo[5] << 16); pl.w = lo[6] | ((uint32_t)lo[7] << 16);
                const int ch = lane * 2 + hf;
                const uint32_t sw = (uint32_t)((ch ^ (warp & 7)) << 4);
                *(uint4*)(sm + OFF_A + aplane + warp * 1024 + sw) = ph;
                *(uint4*)(sm + OFF_A + aplane + (warp + 8) * 1024 + sw) = pl;
            }
        }
        __syncthreads();   // A plane complete before any warp's G reads it

        // ---- phase G: A from smem (plane pr), B from registers ----
        float acc[4][4];
#pragma unroll
        for (int s4 = 0; s4 < 4; s4++)
#pragma unroll
            for (int e = 0; e < 4; e++) acc[s4][e] = 0.f;
#pragma unroll
        for (int ks = 0; ks < 32; ks++) {
            uint32_t aF[4];
            ldmatrix_x4(aF[0], aF[1], aF[2], aF[3],
                        aRowBase + aplane + (uint32_t)((((2 * ks + aOff) ^ aSw)) << 4));
            const int p = ks & 1;
            const int i = ks >> 1;
            mma16816(acc[p * 2 + 0], aF, &Bh[4 * i + p * 2]);
            mma16816(acc[p * 2 + 1], aF, &Bl[4 * i + p * 2]);
        }

        // ---- liquid update: h0 = NORMALIZED h read back from A tile (plane pr) ----
        {
            float base0 = acc[0][0] + acc[1][0] + acc[2][0] + acc[3][0]
                        + acc[0][2] + acc[1][2] + acc[2][2] + acc[3][2] + xp.x;
            float base1 = acc[0][1] + acc[1][1] + acc[2][1] + acc[3][1]
                        + acc[0][3] + acc[1][3] + acc[2][3] + acc[3][3] + xp.y;
            const uint32_t swz = ((h0chunk ^ (uint32_t)(r_up & 7)) << 4) + h0off;
            const uint32_t vh = *(uint32_t*)(sm + OFF_A + aplane + r_up * 1024 + swz);
            const uint32_t vl = *(uint32_t*)(sm + OFF_A + aplane + (r_up + 8) * 1024 + swz);
            const float h0 = __bfloat162float(__ushort_as_bfloat16((unsigned short)(vh & 0xffff)))
                           + __bfloat162float(__ushort_as_bfloat16((unsigned short)(vl & 0xffff)));
            const float h1 = __bfloat162float(__ushort_as_bfloat16((unsigned short)(vh >> 16)))
                           + __bfloat162float(__ushort_as_bfloat16((unsigned short)(vl >> 16)));
            const float sg0 = 1.f / (1.f + __expf(-base0));
            const float sg1 = 1.f / (1.f + __expf(-base1));
            const float lt0 = tau2.x * sg0 + 1e-7f;
            const float lt1 = tau2.y * sg1 + 1e-7f;
            const float ns0 = h0 + (base0 - h0) * lt0;
            const float ns1 = h1 + (base1 - h1) * lt1;
            *(float2*)&g_H[pw][(size_t)b_up * U_ + col_up] = make_float2(ns0, ns1);
        }
        __syncwarp();
        if (lane == 0) bar_arrive_release(&g_bar[bblk]);
    }

    // ---- final output (cblk 0 only): wait for all, then normalize g_H[0] rows ----
    if (cblk == 0) {
        if (lane == 0) {
            const int tgt = 64 * T_;
            while (ld_acquire(&g_bar[bblk]) < tgt) { }
        }
        __syncwarp();
        const int row = rb + warp;
        const float4* Hg = (const float4*)&g_H[0][(size_t)row * U_];
        float4 hv[4];
#pragma unroll
        for (int j = 0; j < 4; j++) hv[j] = __ldcg(&Hg[lane * 4 + j]);
        float s = 0.f, q = 0.f;
#pragma unroll
        for (int j = 0; j < 4; j++) {
            s += hv[j].x + hv[j].y + hv[j].z + hv[j].w;
            q += hv[j].x * hv[j].x + hv[j].y * hv[j].y
               + hv[j].z * hv[j].z + hv[j].w * hv[j].w;
        }
#pragma unroll
        for (int o = 16; o > 0; o >>= 1) {
            s += __shfl_xor_sync(0xffffffffu, s, o);
            q += __shfl_xor_sync(0xffffffffu, q, o);
        }
        const float mean = s * (1.f / 512.f);
        const float var = q * (1.f / 512.f) - mean * mean;
        const float rstd = rsqrtf(var + 1e-3f);
#pragma unroll
        for (int j = 0; j < 4; j++) {
            const int c = lane * 16 + j * 4;
            float4 v;
            v.x = GB[c + 0] * (hv[j].x - mean) * rstd + GB[U_ + c + 0];
            v.y = GB[c + 1] * (hv[j].y - mean) * rstd + GB[U_ + c + 1];
            v.z = GB[c + 2] * (hv[j].z - mean) * rstd + GB[U_ + c + 2];
            v.w = GB[c + 3] * (hv[j].w - mean) * rstd + GB[U_ + c + 3];
            *(float4*)&out[(size_t)row * U_ + c] = v;
        }
    }
}

// ================= launch =================
extern "C" void kernel_launch(void* const* d_in, const int* in_sizes, int n_in,
                              void* d_out, int out_size) {
    const float* x     = (const float*)d_in[0];
    const float* w_in  = (const float*)d_in[1];
    const float* w_rec = (const float*)d_in[2];
    const float* bias  = (const float*)d_in[3];
    const float* tau   = (const float*)d_in[4];
    const float* gamma = (const float*)d_in[5];
    const float* beta  = (const float*)d_in[6];
    float* out = (float*)d_out;

    void* pBar = nullptr;
    cudaGetSymbolAddress(&pBar, g_bar);
    cudaMemsetAsync(pBar, 0, sizeof(int) * 16);

    static int attr_set = 0;
    if (!attr_set) {
        cudaFuncSetAttribute(gemm_mma, cudaFuncAttributeMaxDynamicSharedMemorySize, 147456);
        cudaFuncSetAttribute(liquid_scan, cudaFuncAttributeMaxDynamicSharedMemorySize, SCAN_SMEM);
        attr_set = 1;
    }

    conv_x<<<16384, 256>>>(x);
    conv_w<<<dim3(16, 64), 256>>>(w_in);
    conv_wrec<<<dim3(16, 16), 256>>>(w_rec);
    gemm_mma<<<dim3(2, 128), 256, 147456>>>(bias);
    liquid_scan<<<128, 256, SCAN_SMEM>>>(tau, gamma, beta, out);
}

// round 17
// speedup vs baseline: 1.0682x; 1.0682x over previous
#include <cuda_runtime.h>
#include <cuda_bf16.h>
#include <cstdint>

#define B_ 128
#define T_ 128
#define D_ 2048
#define U_ 512

// ================= device scratch =================
__device__ float g_xproj[(size_t)B_ * T_ * U_];          // 32 MB
__device__ float g_H[2][B_ * U_];                        // ping-pong pre-LN state
__device__ int   g_bar[16];
// bf16 hi/lo planes for the x-projection GEMM
__device__ __nv_bfloat16 g_Ahi[(size_t)16384 * 2048];    // 64 MB
__device__ __nv_bfloat16 g_Alo[(size_t)16384 * 2048];    // 64 MB
__device__ __nv_bfloat16 g_Bhi[(size_t)512 * 2048];      // w_in^T hi
__device__ __nv_bfloat16 g_Blo[(size_t)512 * 2048];      // w_in^T lo
// w_rec^T hi/lo ([c][k], k contiguous) for the scan tensor-core GEMM
__device__ __nv_bfloat16 g_WThi[(size_t)512 * 512];      // 512 KB
__device__ __nv_bfloat16 g_WTlo[(size_t)512 * 512];      // 512 KB

// ================= helpers =================
__device__ __forceinline__ uint32_t smem_u32(const void* p) {
    uint32_t a;
    asm("{ .reg .u64 t; cvta.to.shared.u64 t, %1; cvt.u32.u64 %0, t; }" : "=r"(a) : "l"(p));
    return a;
}
__device__ __forceinline__ void cp_async16(uint32_t dst, const void* src) {
    asm volatile("cp.async.cg.shared.global [%0], [%1], 16;" :: "r"(dst), "l"(src) : "memory");
}
__device__ __forceinline__ void ldmatrix_x4(uint32_t& d0, uint32_t& d1, uint32_t& d2, uint32_t& d3,
                                            uint32_t addr) {
    asm volatile("ldmatrix.sync.aligned.m8n8.x4.shared.b16 {%0,%1,%2,%3}, [%4];"
                 : "=r"(d0), "=r"(d1), "=r"(d2), "=r"(d3) : "r"(addr));
}
__device__ __forceinline__ void mma16816(float* c, const uint32_t* a, const uint32_t* b) {
    asm volatile("mma.sync.aligned.m16n8k16.row.col.f32.bf16.bf16.f32 "
                 "{%0,%1,%2,%3}, {%4,%5,%6,%7}, {%8,%9}, {%0,%1,%2,%3};"
                 : "+f"(c[0]), "+f"(c[1]), "+f"(c[2]), "+f"(c[3])
                 : "r"(a[0]), "r"(a[1]), "r"(a[2]), "r"(a[3]), "r"(b[0]), "r"(b[1]));
}
__device__ __forceinline__ void bar_arrive_release(int* addr) {
    asm volatile("red.release.gpu.global.add.s32 [%0], 1;" :: "l"(addr) : "memory");
}
__device__ __forceinline__ int ld_acquire(const int* addr) {
    int v;
    asm volatile("ld.acquire.gpu.global.s32 %0, [%1];" : "=r"(v) : "l"(addr) : "memory");
    return v;
}

// ================= conv: x -> hi/lo bf16 planes =================
__global__ void __launch_bounds__(256) conv_x(const float* __restrict__ x) {
    const size_t i = (size_t)blockIdx.x * 256 + threadIdx.x;
    const size_t e0 = i * 8;
    float4 v0 = *(const float4*)(x + e0);
    float4 v1 = *(const float4*)(x + e0 + 4);
    float v[8] = {v0.x, v0.y, v0.z, v0.w, v1.x, v1.y, v1.z, v1.w};
    unsigned short hs[8], ls[8];
#pragma unroll
    for (int j = 0; j < 8; j++) {
        __nv_bfloat16 h = __float2bfloat16(v[j]);
        __nv_bfloat16 l = __float2bfloat16(v[j] - __bfloat162float(h));
        hs[j] = __bfloat16_as_ushort(h);
        ls[j] = __bfloat16_as_ushort(l);
    }
    uint4 ph, pl;
    ph.x = hs[0] | ((uint32_t)hs[1] << 16); ph.y = hs[2] | ((uint32_t)hs[3] << 16);
    ph.z = hs[4] | ((uint32_t)hs[5] << 16); ph.w = hs[6] | ((uint32_t)hs[7] << 16);
    pl.x = ls[0] | ((uint32_t)ls[1] << 16); pl.y = ls[2] | ((uint32_t)ls[3] << 16);
    pl.z = ls[4] | ((uint32_t)ls[5] << 16); pl.w = ls[6] | ((uint32_t)ls[7] << 16);
    *(uint4*)(g_Ahi + e0) = ph;
    *(uint4*)(g_Alo + e0) = pl;
}

// ================= conv: w_in [2048][512] -> w^T hi/lo [512][2048] =================
__global__ void __launch_bounds__(256) conv_w(const float* __restrict__ w) {
    __shared__ float ts[32][33];
    const int tid = threadIdx.x;
    const int bu = blockIdx.x;
    const int bd = blockIdx.y;
    const int tx = tid & 31, ty = tid >> 5;
#pragma unroll
    for (int j = 0; j < 4; j++) {
        const int dl = ty + 8 * j;
        ts[dl][tx] = w[(size_t)(bd * 32 + dl) * U_ + bu * 32 + tx];
    }
    __syncthreads();
    const int ul = tid >> 3, kg = (tid & 7) * 4;
    const int u = bu * 32 + ul;
    const int kk = bd * 32 + kg;
    unsigned short hs[4], ls[4];
#pragma unroll
    for (int j = 0; j < 4; j++) {
        const float vv = ts[kg + j][ul];
        __nv_bfloat16 h = __float2bfloat16(vv);
        __nv_bfloat16 l = __float2bfloat16(vv - __bfloat162float(h));
        hs[j] = __bfloat16_as_ushort(h);
        ls[j] = __bfloat16_as_ushort(l);
    }
    uint2 ph, pl;
    ph.x = hs[0] | ((uint32_t)hs[1] << 16); ph.y = hs[2] | ((uint32_t)hs[3] << 16);
    pl.x = ls[0] | ((uint32_t)ls[1] << 16); pl.y = ls[2] | ((uint32_t)ls[3] << 16);
    *(uint2*)(g_Bhi + (size_t)u * D_ + kk) = ph;
    *(uint2*)(g_Blo + (size_t)u * D_ + kk) = pl;
}

// ================= conv: w_rec [512][512] -> w_rec^T hi/lo [512][512] =================
__global__ void __launch_bounds__(256) conv_wrec(const float* __restrict__ w) {
    __shared__ float ts[32][33];
    const int tid = threadIdx.x;
    const int bc = blockIdx.x;
    const int bk = blockIdx.y;
    const int tx = tid & 31, ty = tid >> 5;
#pragma unroll
    for (int j = 0; j < 4; j++) {
        const int dl = ty + 8 * j;
        ts[dl][tx] = w[(size_t)(bk * 32 + dl) * U_ + bc * 32 + tx];
    }
    __syncthreads();
    const int ul = tid >> 3, kg = (tid & 7) * 4;
    const int c = bc * 32 + ul;
    const int kk = bk * 32 + kg;
    unsigned short hs[4], ls[4];
#pragma unroll
    for (int j = 0; j < 4; j++) {
        const float vv = ts[kg + j][ul];
        __nv_bfloat16 h = __float2bfloat16(vv);
        __nv_bfloat16 l = __float2bfloat16(vv - __bfloat162float(h));
        hs[j] = __bfloat16_as_ushort(h);
        ls[j] = __bfloat16_as_ushort(l);
    }
    uint2 ph, pl;
    ph.x = hs[0] | ((uint32_t)hs[1] << 16); ph.y = hs[2] | ((uint32_t)hs[3] << 16);
    pl.x = ls[0] | ((uint32_t)ls[1] << 16); pl.y = ls[2] | ((uint32_t)ls[3] << 16);
    *(uint2*)(g_WThi + (size_t)c * U_ + kk) = ph;
    *(uint2*)(g_WTlo + (size_t)c * U_ + kk) = pl;
}

// ================= mma.sync GEMM: 128x256 tile, 4-stage pipeline =================
// stage = A(128x64: 16KB) + B(256x64: 32KB) = 48KB; 4 stages = 192KB
__global__ void __launch_bounds__(256, 1) gemm_mma(const float* __restrict__ bias) {
    extern __shared__ char sm[];
    const uint32_t sb = smem_u32(sm);
    const int tid = threadIdx.x, lane = tid & 31, wid = tid >> 5;
    const int wm = wid & 1;
    const int wn = wid >> 1;
    const int bn = blockIdx.x;
    const int bm = blockIdx.y;

    float acc[4][8][4];
#pragma unroll
    for (int mi = 0; mi < 4; mi++)
#pragma unroll
        for (int nj = 0; nj < 8; nj++)
#pragma unroll
            for (int e = 0; e < 4; e++) acc[mi][nj][e] = 0.f;

    auto load_stage = [&](int s, int kch) {
        const int seg = kch >> 5, ck = kch & 31;
        const __nv_bfloat16* Ab = (seg < 2) ? g_Ahi : g_Alo;
        const __nv_bfloat16* Bb = (seg == 1) ? g_Blo : g_Bhi;
        const uint32_t sA = sb + s * 49152;
        const uint32_t sB = sA + 16384;
#pragma unroll
        for (int i = 0; i < 4; i++) {
            const int cid = tid + 256 * i;
            const int r = cid >> 3, c = cid & 7;
            const uint32_t sw = (uint32_t)((c ^ (r & 7)) << 4);
            cp_async16(sA + r * 128 + sw,
                       Ab + (size_t)(bm * 128 + r) * D_ + ck * 64 + c * 8);
        }
#pragma unroll
        for (int i = 0; i < 8; i++) {
            const int cid = tid + 256 * i;
            const int r = cid >> 3, c = cid & 7;
            const uint32_t sw = (uint32_t)((c ^ (r & 7)) << 4);
            cp_async16(sB + r * 128 + sw,
                       Bb + (size_t)(bn * 256 + r) * D_ + ck * 64 + c * 8);
        }
    };

    load_stage(0, 0);
    asm volatile("cp.async.commit_group;" ::: "memory");
    load_stage(1, 1);
    asm volatile("cp.async.commit_group;" ::: "memory");
    load_stage(2, 2);
    asm volatile("cp.async.commit_group;" ::: "memory");

    for (int k = 0; k < 96; k++) {
        asm volatile("cp.async.wait_group 2;" ::: "memory");
        __syncthreads();
        if (k + 3 < 96) load_stage((k + 3) & 3, k + 3);
        asm volatile("cp.async.commit_group;" ::: "memory");

        const uint32_t sA = sb + (k & 3) * 49152;
        const uint32_t sB = sA + 16384;
#pragma unroll
        for (int kk = 0; kk < 4; kk++) {
            uint32_t aF[4][4];
#pragma unroll
            for (int mi = 0; mi < 4; mi++) {
                const int row = wm * 64 + mi * 16 + (lane & 15);
                const int ch = kk * 2 + (lane >> 4);
                ldmatrix_x4(aF[mi][0], aF[mi][1], aF[mi][2], aF[mi][3],
                            sA + row * 128 + ((ch ^ (row & 7)) << 4));
            }
            uint32_t bF[8][2];
#pragma unroll
            for (int ni = 0; ni < 4; ni++) {
                const int row = wn * 64 + ni * 16 + (lane & 7) + ((lane & 16) >> 1);
                const int ch = kk * 2 + ((lane & 8) >> 3);
                uint32_t r0, r1, r2, r3;
                ldmatrix_x4(r0, r1, r2, r3, sB + row * 128 + ((ch ^ (row & 7)) << 4));
                bF[2 * ni][0] = r0; bF[2 * ni][1] = r1;
                bF[2 * ni + 1][0] = r2; bF[2 * ni + 1][1] = r3;
            }
#pragma unroll
            for (int mi = 0; mi < 4; mi++)
#pragma unroll
                for (int nj = 0; nj < 8; nj++)
                    mma16816(acc[mi][nj], aF[mi], bF[nj]);
        }
    }

#pragma unroll
    for (int mi = 0; mi < 4; mi++) {
        const int row = bm * 128 + wm * 64 + mi * 16 + (lane >> 2);
#pragma unroll
        for (int nj = 0; nj < 8; nj++) {
            const int col = bn * 256 + wn * 64 + nj * 8 + (lane & 3) * 2;
            const float2 bi = *(const float2*)&bias[col];
            float2 v0, v1;
            v0.x = acc[mi][nj][0] + bi.x;
            v0.y = acc[mi][nj][1] + bi.y;
            v1.x = acc[mi][nj][2] + bi.x;
            v1.y = acc[mi][nj][3] + bi.y;
            *(float2*)&g_xproj[(size_t)row * U_ + col] = v0;
            *(float2*)&g_xproj[(size_t)(row + 8) * U_ + col] = v1;
        }
    }
}

// ================= scan: round-13 exact (proven 803us) =================
#define OFF_A    0          // 16*1024 = 16384
#define OFF_WHI  16384      // 65536
#define OFF_WLO  81920      // 65536
#define OFF_GB   147456     // 4096
#define SCAN_SMEM 151552

__global__ void __launch_bounds__(256, 1) liquid_scan(const float* __restrict__ tau,
                                                      const float* __restrict__ gamma,
                                                      const float* __restrict__ beta,
                                                      float* __restrict__ out) {
    extern __shared__ char sm[];
    const uint32_t sb = smem_u32(sm);
    float* GB = (float*)(sm + OFF_GB);

    const int tid = threadIdx.x;
    const int lane = tid & 31;
    const int warp = tid >> 5;
    const int bblk = blockIdx.x >> 3;
    const int cblk = blockIdx.x & 7;
    const int rb = bblk * 8;
    const int cb = cblk * 64;

    const int r_up = lane >> 2;
    const int cl_up = warp * 8 + (lane & 3) * 2;
    const int b_up = rb + r_up;
    const int col_up = cb + cl_up;

    // ---- preload W slice (128 KB) + gamma/beta ----
    for (int i = tid; i < 4096; i += 256) {
        const int row = i >> 6, ch = i & 63;
        const uint32_t sw = (uint32_t)((ch ^ (row & 7)) << 4);
        cp_async16(sb + OFF_WHI + row * 1024 + sw, g_WThi + (size_t)(cb + row) * U_ + ch * 8);
        cp_async16(sb + OFF_WLO + row * 1024 + sw, g_WTlo + (size_t)(cb + row) * U_ + ch * 8);
    }
    asm volatile("cp.async.commit_group;" ::: "memory");
    for (int i = tid; i < U_; i += 256) {
        GB[i] = gamma[i];
        GB[U_ + i] = beta[i];
    }
    const float2 tau2 = *(const float2*)&tau[col_up];
    asm volatile("cp.async.wait_group 0;" ::: "memory");
    __syncthreads();

    // GEMM addressing constants
    const uint32_t aRow = sb + OFF_A + (lane & 15) * 1024;
    const int aOff = lane >> 4;
    const int aSw = lane & 7;
    const uint32_t bRowHi = sb + OFF_WHI + (warp * 8 + (lane & 7)) * 1024;
    const uint32_t bRowLo = bRowHi + 65536;
    const int bOff = (lane >> 3) & 3;
    const int bSw = lane & 7;

    // ---- hoist ALL B (W) fragments into registers ----
    uint32_t Bh[64], Bl[64];
#pragma unroll
    for (int i = 0; i < 16; i++) {
        const uint32_t off = (uint32_t)((((4 * i + bOff) ^ bSw)) << 4);
        ldmatrix_x4(Bh[4 * i], Bh[4 * i + 1], Bh[4 * i + 2], Bh[4 * i + 3], bRowHi + off);
        ldmatrix_x4(Bl[4 * i], Bl[4 * i + 1], Bl[4 * i + 2], Bl[4 * i + 3], bRowLo + off);
    }

    // h0 (NORMALIZED h) readback address within the A tile
    const uint32_t h0chunk = (uint32_t)((cb >> 3) + warp);
    const uint32_t h0off = (uint32_t)((lane & 3) * 4);

    int nbar = 0;

    for (int t = 0; t < T_; t++) {
        const int pr = t & 1;
        const int pw = pr ^ 1;

        // ---- phase L ----
        const float2 xp = *(const float2*)&g_xproj[((size_t)b_up * T_ + t) * U_ + col_up];
        if (t == 0) {
#pragma unroll
            for (int i = 0; i < 4; i++)
                *(uint4*)(sm + OFF_A + tid * 16 + i * 4096) = make_uint4(0, 0, 0, 0);
        } else {
            const float4* Hg = (const float4*)&g_H[pr][(size_t)(rb + warp) * U_];
            float4 hv[4];
#pragma unroll
            for (int j = 0; j < 4; j++) hv[j] = __ldcg(&Hg[lane * 4 + j]);
            float s = 0.f, q = 0.f;
#pragma unroll
            for (int j = 0; j < 4; j++) {
                s += hv[j].x + hv[j].y + hv[j].z + hv[j].w;
                q += hv[j].x * hv[j].x + hv[j].y * hv[j].y
                   + hv[j].z * hv[j].z + hv[j].w * hv[j].w;
            }
#pragma unroll
            for (int o = 16; o > 0; o >>= 1) {
                s += __shfl_xor_sync(0xffffffffu, s, o);
                q += __shfl_xor_sync(0xffffffffu, q, o);
            }
            const float mean = s * (1.f / 512.f);
            const float var = q * (1.f / 512.f) - mean * mean;
            const float rstd = rsqrtf(var + 1e-3f);
#pragma unroll
            for (int hf = 0; hf < 2; hf++) {
                float vals[8];
                *(float4*)&vals[0] = hv[hf * 2];
                *(float4*)&vals[4] = hv[hf * 2 + 1];
                unsigned short hi[8], lo[8];
#pragma unroll
                for (int e = 0; e < 8; e++) {
                    const int c = lane * 16 + hf * 8 + e;
                    const float n = GB[c] * (vals[e] - mean) * rstd + GB[U_ + c];
                    __nv_bfloat16 h = __float2bfloat16(n);
                    __nv_bfloat16 l = __float2bfloat16(n - __bfloat162float(h));
                    hi[e] = __bfloat16_as_ushort(h);
                    lo[e] = __bfloat16_as_ushort(l);
                }
                uint4 ph, pl;
                ph.x = hi[0] | ((uint32_t)hi[1] << 16); ph.y = hi[2] | ((uint32_t)hi[3] << 16);
                ph.z = hi[4] | ((uint32_t)hi[5] << 16); ph.w = hi[6] | ((uint32_t)hi[7] << 16);
                pl.x = lo[0] | ((uint32_t)lo[1] << 16); pl.y = lo[2] | ((uint32_t)lo[3] << 16);
                pl.z = lo[4] | ((uint32_t)lo[5] << 16); pl.w = lo[6] | ((uint32_t)lo[7] << 16);
                const int ch = lane * 2 + hf;
                const uint32_t sw = (uint32_t)((ch ^ (warp & 7)) << 4);
                *(uint4*)(sm + OFF_A + warp * 1024 + sw) = ph;
                *(uint4*)(sm + OFF_A + (warp + 8) * 1024 + sw) = pl;
            }
        }
        __syncthreads();

        // ---- phase G: A from smem, B from registers ----
        float acc[4][4];
#pragma unroll
        for (int s4 = 0; s4 < 4; s4++)
#pragma unroll
            for (int e = 0; e < 4; e++) acc[s4][e] = 0.f;
#pragma unroll
        for (int ks = 0; ks < 32; ks++) {
            uint32_t aF[4];
            ldmatrix_x4(aF[0], aF[1], aF[2], aF[3],
                        aRow + (uint32_t)((((2 * ks + aOff) ^ aSw)) << 4));
            const int p = ks & 1;
            const int i = ks >> 1;
            mma16816(acc[p * 2 + 0], aF, &Bh[4 * i + p * 2]);
            mma16816(acc[p * 2 + 1], aF, &Bl[4 * i + p * 2]);
        }

        // ---- liquid update: h0 = NORMALIZED h from A tile ----
        {
            float base0 = acc[0][0] + acc[1][0] + acc[2][0] + acc[3][0]
                        + acc[0][2] + acc[1][2] + acc[2][2] + acc[3][2] + xp.x;
            float base1 = acc[0][1] + acc[1][1] + acc[2][1] + acc[3][1]
                        + acc[0][3] + acc[1][3] + acc[2][3] + acc[3][3] + xp.y;
            const uint32_t swz = ((h0chunk ^ (uint32_t)(r_up & 7)) << 4) + h0off;
            const uint32_t vh = *(uint32_t*)(sm + OFF_A + r_up * 1024 + swz);
            const uint32_t vl = *(uint32_t*)(sm + OFF_A + (r_up + 8) * 1024 + swz);
            const float h0 = __bfloat162float(__ushort_as_bfloat16((unsigned short)(vh & 0xffff)))
                           + __bfloat162float(__ushort_as_bfloat16((unsigned short)(vl & 0xffff)));
            const float h1 = __bfloat162float(__ushort_as_bfloat16((unsigned short)(vh >> 16)))
                           + __bfloat162float(__ushort_as_bfloat16((unsigned short)(vl >> 16)));
            const float sg0 = 1.f / (1.f + __expf(-base0));
            const float sg1 = 1.f / (1.f + __expf(-base1));
            const float lt0 = tau2.x * sg0 + 1e-7f;
            const float lt1 = tau2.y * sg1 + 1e-7f;
            const float ns0 = h0 + (base0 - h0) * lt0;
            const float ns1 = h1 + (base1 - h1) * lt1;
            *(float2*)&g_H[pw][(size_t)b_up * U_ + col_up] = make_float2(ns0, ns1);
        }

        // ---- one release/acquire barrier per step (tid0 spin, proven) ----
        __syncthreads();
        nbar++;
        if (tid == 0) {
            bar_arrive_release(&g_bar[bblk]);
            while (ld_acquire(&g_bar[bblk]) < 8 * nbar) { }
        }
        __syncthreads();
    }

    // ---- final output (cblk 0 only) ----
    if (cblk == 0) {
        const int row = rb + warp;
        const float4* Hg = (const float4*)&g_H[0][(size_t)row * U_];
        float4 hv[4];
#pragma unroll
        for (int j = 0; j < 4; j++) hv[j] = __ldcg(&Hg[lane * 4 + j]);
        float s = 0.f, q = 0.f;
#pragma unroll
        for (int j = 0; j < 4; j++) {
            s += hv[j].x + hv[j].y + hv[j].z + hv[j].w;
            q += hv[j].x * hv[j].x + hv[j].y * hv[j].y
               + hv[j].z * hv[j].z + hv[j].w * hv[j].w;
        }
#pragma unroll
        for (int o = 16; o > 0; o >>= 1) {
            s += __shfl_xor_sync(0xffffffffu, s, o);
            q += __shfl_xor_sync(0xffffffffu, q, o);
        }
        const float mean = s * (1.f / 512.f);
        const float var = q * (1.f / 512.f) - mean * mean;
        const float rstd = rsqrtf(var + 1e-3f);
#pragma unroll
        for (int j = 0; j < 4; j++) {
            const int c = lane * 16 + j * 4;
            float4 v;
            v.x = GB[c + 0] * (hv[j].x - mean) * rstd + GB[U_ + c + 0];
            v.y = GB[c + 1] * (hv[j].y - mean) * rstd + GB[U_ + c + 1];
            v.z = GB[c + 2] * (hv[j].z - mean) * rstd + GB[U_ + c + 2];
            v.w = GB[c + 3] * (hv[j].w - mean) * rstd + GB[U_ + c + 3];
            *(float4*)&out[(size_t)row * U_ + c] = v;
        }
    }
}

// ================= launch =================
extern "C" void kernel_launch(void* const* d_in, const int* in_sizes, int n_in,
                              void* d_out, int out_size) {
    const float* x     = (const float*)d_in[0];
    const float* w_in  = (const float*)d_in[1];
    const float* w_rec = (const float*)d_in[2];
    const float* bias  = (const float*)d_in[3];
    const float* tau   = (const float*)d_in[4];
    const float* gamma = (const float*)d_in[5];
    const float* beta  = (const float*)d_in[6];
    float* out = (float*)d_out;

    void* pBar = nullptr;
    cudaGetSymbolAddress(&pBar, g_bar);
    cudaMemsetAsync(pBar, 0, sizeof(int) * 16);

    static int attr_set = 0;
    if (!attr_set) {
        cudaFuncSetAttribute(gemm_mma, cudaFuncAttributeMaxDynamicSharedMemorySize, 196608);
        cudaFuncSetAttribute(liquid_scan, cudaFuncAttributeMaxDynamicSharedMemorySize, SCAN_SMEM);
        attr_set = 1;
    }

    conv_x<<<16384, 256>>>(x);
    conv_w<<<dim3(16, 64), 256>>>(w_in);
    conv_wrec<<<dim3(16, 16), 256>>>(w_rec);
    gemm_mma<<<dim3(2, 128), 256, 196608>>>(bias);
    liquid_scan<<<128, 256, SCAN_SMEM>>>(tau, gamma, beta, out);
}